// round 11
// baseline (speedup 1.0000x reference)
#include <cuda_runtime.h>

// exp(Q*t) for 2,097,152 independent 4x4 fp32 matrices.
// R11: LANE-PAIRED formulation — each thread computes TWO matrices, with
// matrix 1 in the LOW f32 lane and matrix 2 in the HIGH lane of every
// packed f32x2 register. A 4x4 matmul is then PURELY ELEMENTWISE packed
// arithmetic: C[i][j] = sum_k A[i][k]*B[k][j] with every operand already a
// {m1,m2} pair — ZERO broadcast movs (R6 spent ~40% of its fma-pipe slots
// on pack2 broadcast MOVs). Polynomial: degree-8 Taylor via even/odd
// Paterson-Stockmeyer in Y=X^2:
//   P = (I+X) + Y*(B1 + Y*(B2 + Y*(B3 + c8*Y))),  Bj = c2j*I + c2j+1*X
// (4 matmuls; Bj folded into accumulator inits -> no block storage).
// Squaring loop is also mov-free. Register peak = 64 u64 (X, Y, ping, pong);
// launch_bounds(128,3) caps at 170 regs -> no spills (R8 lesson).

#define SEQ_SHIFT 15
#define NMAT (64 * 32768)
#define NPAIR (NMAT / 2)
#define TPB 128

typedef unsigned long long u64;

__device__ __forceinline__ u64 pack2(float lo, float hi) {
    u64 r; asm("mov.b64 %0, {%1, %2};" : "=l"(r) : "f"(lo), "f"(hi)); return r;
}
__device__ __forceinline__ void unpack2(u64 v, float& lo, float& hi) {
    asm("mov.b64 {%0, %1}, %2;" : "=f"(lo), "=f"(hi) : "l"(v));
}
__device__ __forceinline__ u64 fma2(u64 a, u64 b, u64 c) {
    u64 d; asm("fma.rn.f32x2 %0, %1, %2, %3;" : "=l"(d) : "l"(a), "l"(b), "l"(c)); return d;
}
__device__ __forceinline__ u64 mul2(u64 a, u64 b) {
    u64 d; asm("mul.rn.f32x2 %0, %1, %2;" : "=l"(d) : "l"(a), "l"(b)); return d;
}
__device__ __forceinline__ u64 add2(u64 a, u64 b) {
    u64 d; asm("add.rn.f32x2 %0, %1, %2;" : "=l"(d) : "l"(a), "l"(b)); return d;
}
__device__ __forceinline__ u64 abs2(u64 v) { return v & 0x7FFFFFFF7FFFFFFFull; }

// Elementwise-paired 4x4 matmul: C = A*B (no additive term).
__device__ __forceinline__ void mmp(const u64* __restrict__ A,
                                    const u64* __restrict__ B,
                                    u64* __restrict__ C) {
#pragma unroll
    for (int i = 0; i < 4; ++i) {
#pragma unroll
        for (int j = 0; j < 4; ++j) {
            u64 acc = mul2(A[4 * i + 0], B[0 + j]);
            acc = fma2(A[4 * i + 1], B[4 + j], acc);
            acc = fma2(A[4 * i + 2], B[8 + j], acc);
            acc = fma2(A[4 * i + 3], B[12 + j], acc);
            C[4 * i + j] = acc;
        }
    }
}

// C = Y*H + (a*I + b*X)  -- PS Horner step with the block computed on the fly
// inside the accumulator init (1 extra fma2 per element, zero block storage).
__device__ __forceinline__ void mmp_blk(const u64* __restrict__ Y,
                                        const u64* __restrict__ H,
                                        const u64* __restrict__ X,
                                        float a, float b,
                                        u64* __restrict__ C) {
    const u64 bp = pack2(b, b);
    const u64 ap = pack2(a, a);
#pragma unroll
    for (int i = 0; i < 4; ++i) {
#pragma unroll
        for (int j = 0; j < 4; ++j) {
            const int e = 4 * i + j;
            u64 d = fma2(X[e], bp, (i == j) ? ap : 0ull);   // a*I + b*X
            d = fma2(Y[4 * i + 0], H[0 + j], d);
            d = fma2(Y[4 * i + 1], H[4 + j], d);
            d = fma2(Y[4 * i + 2], H[8 + j], d);
            d = fma2(Y[4 * i + 3], H[12 + j], d);
            C[e] = d;
        }
    }
}

// C = Y*H + G  (G a full additive matrix).
__device__ __forceinline__ void mmp_add(const u64* __restrict__ Y,
                                        const u64* __restrict__ H,
                                        const u64* __restrict__ G,
                                        u64* __restrict__ C) {
#pragma unroll
    for (int i = 0; i < 4; ++i) {
#pragma unroll
        for (int j = 0; j < 4; ++j) {
            u64 d = fma2(Y[4 * i + 0], H[0 + j], G[4 * i + j]);
            d = fma2(Y[4 * i + 1], H[4 + j], d);
            d = fma2(Y[4 * i + 2], H[8 + j], d);
            d = fma2(Y[4 * i + 3], H[12 + j], d);
            C[4 * i + j] = d;
        }
    }
}

__global__ __launch_bounds__(TPB, 3)
void expm44_kernel(const float* __restrict__ rate,   // [NMAT, 16]
                   const float* __restrict__ time,   // [64]
                   float* __restrict__ out)          // [NMAT, 16]
{
    const int p = blockIdx.x * TPB + threadIdx.x;     // pair id; grid exact
    // matrices 2p and 2p+1 (always in the same batch row -> same t)
    const float t = __ldg(time + (p >> (SEQ_SHIFT - 1)));

    // Load 128B (two matrices) with 8 front-batched LDG.128 (streaming).
    const ulonglong2* ap = reinterpret_cast<const ulonglong2*>(rate) + (size_t)p * 8;
    ulonglong2 l[8];
#pragma unroll
    for (int k = 0; k < 8; ++k) l[k] = __ldcs(ap + k);

    // Interleave into lane-paired form: X[e] = {M1[e], M2[e]} (one-time movs).
    u64 X[16];
#pragma unroll
    for (int k = 0; k < 4; ++k) {
        float a0, a1, a2, a3, b0, b1, b2, b3;
        unpack2(l[k].x, a0, a1);     unpack2(l[k].y, a2, a3);       // M1
        unpack2(l[4 + k].x, b0, b1); unpack2(l[4 + k].y, b2, b3);   // M2
        X[4 * k + 0] = pack2(a0, b0);
        X[4 * k + 1] = pack2(a1, b1);
        X[4 * k + 2] = pack2(a2, b2);
        X[4 * k + 3] = pack2(a3, b3);
    }

    // inf-norms of both matrices at once (abs=ALU AND, row sums packed).
    u64 r0 = add2(add2(abs2(X[0]),  abs2(X[1])),  add2(abs2(X[2]),  abs2(X[3])));
    u64 r1 = add2(add2(abs2(X[4]),  abs2(X[5])),  add2(abs2(X[6]),  abs2(X[7])));
    u64 r2 = add2(add2(abs2(X[8]),  abs2(X[9])),  add2(abs2(X[10]), abs2(X[11])));
    u64 r3 = add2(add2(abs2(X[12]), abs2(X[13])), add2(abs2(X[14]), abs2(X[15])));
    float m10, m20, m11, m21, m12, m22, m13, m23;
    unpack2(r0, m10, m20); unpack2(r1, m11, m21);
    unpack2(r2, m12, m22); unpack2(r3, m13, m23);
    const float n1 = fmaxf(fmaxf(m10, m11), fmaxf(m12, m13)) * t;
    const float n2 = fmaxf(fmaxf(m20, m21), fmaxf(m22, m23)) * t;

    // s ~ ceil(log2(n)) via exponent bits; clamp [0,16]; max over pair + warp.
    int s1 = (int)(__float_as_uint(n1) >> 23) - 126;
    int s2 = (int)(__float_as_uint(n2) >> 23) - 126;
    int sb = max(max(s1, s2), 0);
    sb = min(sb, 16);
    const unsigned sw = __reduce_max_sync(0xFFFFFFFFu, (unsigned)sb);

    // X = M * (t * 2^-sw), in place.
    const float scale = t * __uint_as_float((127u - sw) << 23);
    const u64 sc2 = pack2(scale, scale);
#pragma unroll
    for (int e = 0; e < 16; ++e) X[e] = mul2(X[e], sc2);

    // Y = X^2
    u64 Y[16];
    mmp(X, X, Y);

    // Taylor coefficients 1/k!
    const float c2 = 1.0f / 2.0f,   c3 = 1.0f / 6.0f,    c4 = 1.0f / 24.0f;
    const float c5 = 1.0f / 120.0f, c6 = 1.0f / 720.0f,  c7 = 1.0f / 5040.0f;
    const float c8 = 1.0f / 40320.0f;

    // H3 = c8*Y + c6*I + c7*X   (elementwise, no matmul)
    u64 Ha[16], Hb[16];
    {
        const u64 c8p = pack2(c8, c8), c7p = pack2(c7, c7), c6p = pack2(c6, c6);
#pragma unroll
        for (int i = 0; i < 4; ++i)
#pragma unroll
            for (int j = 0; j < 4; ++j) {
                const int e = 4 * i + j;
                u64 d = fma2(X[e], c7p, (i == j) ? c6p : 0ull);
                Ha[e] = fma2(Y[e], c8p, d);
            }
    }

    // H2 = Y*H3 + (c4 I + c5 X) ; H1 = Y*H2 + (c2 I + c3 X)
    mmp_blk(Y, Ha, X, c4, c5, Hb);
    mmp_blk(Y, Hb, X, c2, c3, Ha);

    // G = I + X (in place on X; X is dead as "X" after this)
    {
        const u64 one = pack2(1.0f, 1.0f);
        X[0]  = add2(X[0],  one);
        X[5]  = add2(X[5],  one);
        X[10] = add2(X[10], one);
        X[15] = add2(X[15], one);
    }

    // P = Y*H1 + G   (P lives in Hb)
    mmp_add(Y, Ha, X, Hb);

    // Square sw times (warp-uniform; squaring is mov-free elementwise matmul).
    for (unsigned q = 0; q < sw; ++q) {
        mmp(Hb, Hb, Ha);
#pragma unroll
        for (int e = 0; e < 16; ++e) Hb[e] = Ha[e];
    }

    // De-interleave and store both matrices (8x STG.128, streaming).
    ulonglong2* op = reinterpret_cast<ulonglong2*>(out) + (size_t)p * 8;
#pragma unroll
    for (int k = 0; k < 4; ++k) {
        float a0, b0, a1, b1, a2, b2, a3, b3;
        unpack2(Hb[4 * k + 0], a0, b0);
        unpack2(Hb[4 * k + 1], a1, b1);
        unpack2(Hb[4 * k + 2], a2, b2);
        unpack2(Hb[4 * k + 3], a3, b3);
        __stcs(op + k,     make_ulonglong2(pack2(a0, a1), pack2(a2, a3)));   // M1
        __stcs(op + 4 + k, make_ulonglong2(pack2(b0, b1), pack2(b2, b3)));   // M2
    }
}

extern "C" void kernel_launch(void* const* d_in, const int* in_sizes, int n_in,
                              void* d_out, int out_size) {
    const float* rate = (const float*)d_in[0];
    const float* time = (const float*)d_in[1];
    float* out = (float*)d_out;

    expm44_kernel<<<NPAIR / TPB, TPB>>>(rate, time, out);
}